// round 5
// baseline (speedup 1.0000x reference)
#include <cuda_runtime.h>
#include <cuda_bf16.h>
#include <stdint.h>

#define SDIM    16
#define KDIM    4096
#define ODIM    14336
#define GSIZE   256
#define NGROUPS (KDIM / GSIZE)   // 16
#define KSPLIT  2
#define GPERCTA (NGROUPS / KSPLIT) // 8
#define TILE_O  32
#define NTHREADS 128
#define STRIDE  264              // bf16 elems per smem row; 528B row stride -> 4-bank shift/row, LDSM conflict-free

// Precomputed x split into bf16 hi + lo residual (written by prologue kernel)
__device__ __align__(16) __nv_bfloat16 g_xh[SDIM * KDIM];
__device__ __align__(16) __nv_bfloat16 g_xl[SDIM * KDIM];

static __device__ __forceinline__ uint32_t packbf(__nv_bfloat16 a, __nv_bfloat16 b) {
    __nv_bfloat162 t = __halves2bfloat162(a, b);
    return *reinterpret_cast<uint32_t*>(&t);
}

static __device__ __forceinline__ void mma16816(
    float& d0, float& d1, float& d2, float& d3,
    uint32_t a0, uint32_t a1, uint32_t a2, uint32_t a3,
    uint32_t b0, uint32_t b1)
{
    asm volatile(
        "mma.sync.aligned.m16n8k16.row.col.f32.bf16.bf16.f32 "
        "{%0,%1,%2,%3}, {%4,%5,%6,%7}, {%8,%9}, {%0,%1,%2,%3};\n"
        : "+f"(d0), "+f"(d1), "+f"(d2), "+f"(d3)
        : "r"(a0), "r"(a1), "r"(a2), "r"(a3), "r"(b0), "r"(b1));
}

static __device__ __forceinline__ void ldsm_x4(
    uint32_t& r0, uint32_t& r1, uint32_t& r2, uint32_t& r3, uint32_t saddr)
{
    asm volatile("ldmatrix.sync.aligned.m8n8.x4.shared.b16 {%0,%1,%2,%3}, [%4];\n"
        : "=r"(r0), "=r"(r1), "=r"(r2), "=r"(r3) : "r"(saddr));
}

static __device__ __forceinline__ void ldsm_x2(
    uint32_t& r0, uint32_t& r1, uint32_t saddr)
{
    asm volatile("ldmatrix.sync.aligned.m8n8.x2.shared.b16 {%0,%1}, [%2];\n"
        : "=r"(r0), "=r"(r1) : "r"(saddr));
}

static __device__ __forceinline__ void cp16(uint32_t sdst, const void* gsrc)
{
    asm volatile("cp.async.ca.shared.global [%0], [%1], 16;\n"
        :: "r"(sdst), "l"(gsrc));
}

// Fused prologue: zero the output (blocks 0..223) + split x into bf16 hi/lo (blocks 224..287)
#define ZBLOCKS 224   // 16*14336 floats / (256 thr * 4)
__global__ void prologue_kernel(const float* __restrict__ x, float4* __restrict__ out)
{
    const int bid = blockIdx.x;
    if (bid < ZBLOCKS) {
        out[bid * 256 + threadIdx.x] = make_float4(0.f, 0.f, 0.f, 0.f);
    } else {
        const int t = (bid - ZBLOCKS) * 256 + threadIdx.x;   // 0..16383, one float4 each
        const float4 v = ((const float4*)x)[t];
        __nv_bfloat16 hx = __float2bfloat16_rn(v.x);
        __nv_bfloat16 hy = __float2bfloat16_rn(v.y);
        __nv_bfloat16 hz = __float2bfloat16_rn(v.z);
        __nv_bfloat16 hw = __float2bfloat16_rn(v.w);
        uint2 hv;
        hv.x = packbf(hx, hy);
        hv.y = packbf(hz, hw);
        *(uint2*)&g_xh[t * 4] = hv;
        uint2 lv;
        lv.x = packbf(__float2bfloat16_rn(v.x - __bfloat162float(hx)),
                      __float2bfloat16_rn(v.y - __bfloat162float(hy)));
        lv.y = packbf(__float2bfloat16_rn(v.z - __bfloat162float(hz)),
                      __float2bfloat16_rn(v.w - __bfloat162float(hw)));
        *(uint2*)&g_xl[t * 4] = lv;
    }
}

__global__ void __launch_bounds__(NTHREADS, 4)
qlinear_int4_kernel(const float* __restrict__ w, float* __restrict__ out)
{
    __shared__ __nv_bfloat16 sxh[SDIM][STRIDE];   // x high bf16
    __shared__ __nv_bfloat16 sxl[SDIM][STRIDE];   // x low  bf16 (residual)
    __shared__ __nv_bfloat16 swq[TILE_O][STRIDE]; // quantized w_int as bf16
    __shared__ float sscale[TILE_O];

    const int tid  = threadIdx.x;
    const int lane = tid & 31;
    const int wid  = tid >> 5;       // warp 0..3, owns n8 tile wid
    const int tg   = lane & 3;       // 0..3
    const int gid  = lane >> 2;      // 0..7
    const int obase = blockIdx.x * TILE_O;
    const int g0base = blockIdx.y * GPERCTA;   // K-split: this CTA's first group

    // W tile load mapping: 4 threads per output row, 64B contiguous per row per instr
    const int wr = tid >> 2;         // row in tile 0..31
    const int wc = tid & 3;          // chunk 0..3
    const float* wrow = w + (size_t)(obase + wr) * KDIM;

    // x cp.async mapping: 64 threads per tensor (hi/lo), 4 threads per s-row, 128B each
    const int xsel = tid >> 6;       // 0 = hi, 1 = lo
    const int xt   = tid & 63;
    const int xr   = xt >> 2;        // 0..15
    const int xcq  = xt & 3;         // 0..3 (128B chunk of the 512B row)
    const __nv_bfloat16* xsrc = (xsel ? g_xl : g_xh) + (size_t)xr * KDIM + xcq * 64;
    const uint32_t xdst = (uint32_t)__cvta_generic_to_shared(
        xsel ? &sxl[xr][xcq * 64] : &sxh[xr][xcq * 64]);

    float facc0 = 0.f, facc1 = 0.f, facc2 = 0.f, facc3 = 0.f;

    // ldmatrix base addresses (shared space)
    const uint32_t a_xh = (uint32_t)__cvta_generic_to_shared(&sxh[lane & 15][8 * (lane >> 4)]);
    const uint32_t a_xl = (uint32_t)__cvta_generic_to_shared(&sxl[lane & 15][8 * (lane >> 4)]);
    const uint32_t a_b  = (uint32_t)__cvta_generic_to_shared(&swq[wid * 8 + (lane & 7)][8 * ((lane >> 3) & 1)]);

    // ---- prologue: load first W group into registers ----
    float4 wv[16];
    {
        const int kb = g0base * GSIZE;
        #pragma unroll
        for (int i = 0; i < 16; ++i)
            wv[i] = *(const float4*)(wrow + kb + (wc + 4 * i) * 4);
    }

    for (int gi = 0; gi < GPERCTA; ++gi) {
        const int kb = (g0base + gi) * GSIZE;

        // ---- per-row group max (exact: thread-local + 2x shfl across the 4-lane row group)
        float m = 0.f;
        #pragma unroll
        for (int i = 0; i < 16; ++i) {
            m = fmaxf(m, fabsf(wv[i].x));
            m = fmaxf(m, fabsf(wv[i].y));
            m = fmaxf(m, fabsf(wv[i].z));
            m = fmaxf(m, fabsf(wv[i].w));
        }
        m = fmaxf(m, __shfl_xor_sync(0xffffffffu, m, 1));
        m = fmaxf(m, __shfl_xor_sync(0xffffffffu, m, 2));
        const float scale = fmaxf(m / 7.0f, 1e-9f);
        const float rcp   = 1.0f / scale;

        __syncthreads();   // previous group's LDSM reads done before smem overwrite

        // ---- stage x tiles (bf16 hi/lo, precomputed) via cp.async ----
        {
            const __nv_bfloat16* s = xsrc + kb;
            #pragma unroll
            for (int j = 0; j < 8; ++j)
                cp16(xdst + j * 16, s + j * 8);
            asm volatile("cp.async.commit_group;\n");
        }

        // ---- quantize W -> bf16 w_int into smem ----
        #pragma unroll
        for (int i = 0; i < 16; ++i) {
            const int col = (wc + 4 * i) * 4;
            const float4 v = wv[i];
            float q0 = fminf(fmaxf(rintf(v.x * rcp), -8.f), 7.f);
            float q1 = fminf(fmaxf(rintf(v.y * rcp), -8.f), 7.f);
            float q2 = fminf(fmaxf(rintf(v.z * rcp), -8.f), 7.f);
            float q3 = fminf(fmaxf(rintf(v.w * rcp), -8.f), 7.f);
            uint2 pk;
            pk.x = packbf(__float2bfloat16_rn(q0), __float2bfloat16_rn(q1));
            pk.y = packbf(__float2bfloat16_rn(q2), __float2bfloat16_rn(q3));
            *(uint2*)&swq[wr][col] = pk;
        }
        if (wc == 0) sscale[wr] = scale;

        // ---- prefetch next W tile (wv dead after quantize) ----
        if (gi + 1 < GPERCTA) {
            const int kbn = kb + GSIZE;
            #pragma unroll
            for (int i = 0; i < 16; ++i)
                wv[i] = *(const float4*)(wrow + kbn + (wc + 4 * i) * 4);
        }

        asm volatile("cp.async.wait_group 0;\n");
        __syncthreads();

        // ---- MMA phase: 16 k-steps x (hi + lo), group-local fp32 accumulators ----
        float p0 = 0.f, p1 = 0.f, p2 = 0.f, p3 = 0.f;
        #pragma unroll
        for (int ks = 0; ks < 16; ++ks) {
            const uint32_t boff = ks * 32;  // 16 bf16 = 32 bytes per k-step
            uint32_t b0, b1;
            ldsm_x2(b0, b1, a_b + boff);

            uint32_t h0, h1, h2, h3;
            ldsm_x4(h0, h1, h2, h3, a_xh + boff);
            mma16816(p0, p1, p2, p3, h0, h1, h2, h3, b0, b1);

            uint32_t l0, l1, l2, l3;
            ldsm_x4(l0, l1, l2, l3, a_xl + boff);
            mma16816(p0, p1, p2, p3, l0, l1, l2, l3, b0, b1);
        }

        // scale per output column (o), accumulate into final
        const float se = sscale[wid * 8 + 2 * tg];
        const float so = sscale[wid * 8 + 2 * tg + 1];
        facc0 += se * p0;
        facc1 += so * p1;
        facc2 += se * p2;
        facc3 += so * p3;
    }

    // ---- epilogue: atomic accumulate split-K partials (spread addresses -> RED) ----
    const int ocol = obase + wid * 8 + 2 * tg;
    const int r0 = gid;
    const int r1 = gid + 8;
    atomicAdd(out + (size_t)r0 * ODIM + ocol,     facc0);
    atomicAdd(out + (size_t)r0 * ODIM + ocol + 1, facc1);
    atomicAdd(out + (size_t)r1 * ODIM + ocol,     facc2);
    atomicAdd(out + (size_t)r1 * ODIM + ocol + 1, facc3);
}

extern "C" void kernel_launch(void* const* d_in, const int* in_sizes, int n_in,
                              void* d_out, int out_size)
{
    (void)in_sizes; (void)n_in; (void)out_size;
    const float* x = (const float*)d_in[0];   // [1,16,4096]
    const float* w = (const float*)d_in[1];   // [14336,4096]
    float* out = (float*)d_out;               // [1,16,14336]

    // allow full smem carveout so 4 CTAs/SM are never carveout-blocked
    cudaFuncSetAttribute(qlinear_int4_kernel,
                         cudaFuncAttributePreferredSharedMemoryCarveout, 100);

    // prologue: zero output + precompute x hi/lo bf16
    prologue_kernel<<<ZBLOCKS + (SDIM * KDIM) / (256 * 4), 256>>>(x, (float4*)out);

    dim3 grid(ODIM / TILE_O, KSPLIT);  // (448, 2)
    dim3 block(NTHREADS);              // 128
    qlinear_int4_kernel<<<grid, block>>>(w, out);
}

// round 6
// speedup vs baseline: 1.6648x; 1.6648x over previous
#include <cuda_runtime.h>
#include <cuda_bf16.h>
#include <stdint.h>

#define SDIM    16
#define KDIM    4096
#define ODIM    14336
#define GSIZE   256
#define NGROUPS (KDIM / GSIZE)   // 16
#define TILE_O  32
#define NTHREADS 128
#define STRIDE  264              // bf16 elems per smem row; 528B row stride -> 4-bank shift/row, LDSM conflict-free

// Precomputed x split into bf16 hi + lo residual (written by prologue kernel)
__device__ __align__(16) __nv_bfloat16 g_xh[SDIM * KDIM];
__device__ __align__(16) __nv_bfloat16 g_xl[SDIM * KDIM];

static __device__ __forceinline__ uint32_t packbf(__nv_bfloat16 a, __nv_bfloat16 b) {
    __nv_bfloat162 t = __halves2bfloat162(a, b);
    return *reinterpret_cast<uint32_t*>(&t);
}

// pack two fp32 -> bf16x2 in ONE cvt (result = {lo=a, hi=b})
static __device__ __forceinline__ uint32_t cvt_bf16x2(float a, float b) {
    uint32_t r;
    asm("cvt.rn.bf16x2.f32 %0, %1, %2;" : "=r"(r) : "f"(b), "f"(a));
    return r;
}

static __device__ __forceinline__ void mma16816(
    float& d0, float& d1, float& d2, float& d3,
    uint32_t a0, uint32_t a1, uint32_t a2, uint32_t a3,
    uint32_t b0, uint32_t b1)
{
    asm volatile(
        "mma.sync.aligned.m16n8k16.row.col.f32.bf16.bf16.f32 "
        "{%0,%1,%2,%3}, {%4,%5,%6,%7}, {%8,%9}, {%0,%1,%2,%3};\n"
        : "+f"(d0), "+f"(d1), "+f"(d2), "+f"(d3)
        : "r"(a0), "r"(a1), "r"(a2), "r"(a3), "r"(b0), "r"(b1));
}

static __device__ __forceinline__ void ldsm_x4(
    uint32_t& r0, uint32_t& r1, uint32_t& r2, uint32_t& r3, uint32_t saddr)
{
    asm volatile("ldmatrix.sync.aligned.m8n8.x4.shared.b16 {%0,%1,%2,%3}, [%4];\n"
        : "=r"(r0), "=r"(r1), "=r"(r2), "=r"(r3) : "r"(saddr));
}

static __device__ __forceinline__ void ldsm_x2(
    uint32_t& r0, uint32_t& r1, uint32_t saddr)
{
    asm volatile("ldmatrix.sync.aligned.m8n8.x2.shared.b16 {%0,%1}, [%2];\n"
        : "=r"(r0), "=r"(r1) : "r"(saddr));
}

// Prologue: split x into bf16 hi/lo (16384 float4s over 64 blocks x 256 thr)
__global__ void xsplit_kernel(const float* __restrict__ x)
{
    const int t = blockIdx.x * 256 + threadIdx.x;   // 0..16383, one float4 each
    const float4 v = ((const float4*)x)[t];
    __nv_bfloat16 hx = __float2bfloat16_rn(v.x);
    __nv_bfloat16 hy = __float2bfloat16_rn(v.y);
    __nv_bfloat16 hz = __float2bfloat16_rn(v.z);
    __nv_bfloat16 hw = __float2bfloat16_rn(v.w);
    uint2 hv;
    hv.x = packbf(hx, hy);
    hv.y = packbf(hz, hw);
    *(uint2*)&g_xh[t * 4] = hv;
    uint2 lv;
    lv.x = cvt_bf16x2(v.x - __bfloat162float(hx), v.y - __bfloat162float(hy));
    lv.y = cvt_bf16x2(v.z - __bfloat162float(hz), v.w - __bfloat162float(hw));
    *(uint2*)&g_xl[t * 4] = lv;
}

__global__ void __launch_bounds__(NTHREADS, 3)
qlinear_int4_kernel(const float* __restrict__ w, float* __restrict__ out)
{
    __shared__ __nv_bfloat16 sxh[SDIM][STRIDE];   // x high bf16
    __shared__ __nv_bfloat16 sxl[SDIM][STRIDE];   // x low  bf16 (residual)
    __shared__ __nv_bfloat16 swq[TILE_O][STRIDE]; // quantized w_int as bf16
    __shared__ float sscale[TILE_O];

    const int tid  = threadIdx.x;
    const int lane = tid & 31;
    const int wid  = tid >> 5;       // warp 0..3, owns n8 tile wid
    const int tg   = lane & 3;       // 0..3
    const int gid  = lane >> 2;      // 0..7
    const int obase = blockIdx.x * TILE_O;

    // W tile load mapping: 4 threads per output row, 64B contiguous per row per instr
    const int wr = tid >> 2;         // row in tile 0..31
    const int wc = tid & 3;          // chunk 0..3
    const float* wrow = w + (size_t)(obase + wr) * KDIM;

    // x staging mapping: 8 threads per s-row; thread copies 4x16B (stride 8 units -> conflict-free STS.128)
    const int xr  = tid >> 3;        // 0..15
    const int xcu = tid & 7;         // base 16B-unit
    const __nv_bfloat16* xsrc_h = g_xh + (size_t)xr * KDIM;
    const __nv_bfloat16* xsrc_l = g_xl + (size_t)xr * KDIM;

    float facc0 = 0.f, facc1 = 0.f, facc2 = 0.f, facc3 = 0.f;

    // ldmatrix base addresses (shared space)
    const uint32_t a_xh = (uint32_t)__cvta_generic_to_shared(&sxh[lane & 15][8 * (lane >> 4)]);
    const uint32_t a_xl = (uint32_t)__cvta_generic_to_shared(&sxl[lane & 15][8 * (lane >> 4)]);
    const uint32_t a_b  = (uint32_t)__cvta_generic_to_shared(&swq[wid * 8 + (lane & 7)][8 * ((lane >> 3) & 1)]);

    // ---- prologue: load group 0 W into registers ----
    float4 wv[16];
    #pragma unroll
    for (int i = 0; i < 16; ++i)
        wv[i] = *(const float4*)(wrow + (wc + 4 * i) * 4);

    for (int g = 0; g < NGROUPS; ++g) {
        const int kb = g * GSIZE;

        // ---- per-row group max (exact: thread-local + 2x shfl across the 4-lane row group)
        float m = 0.f;
        #pragma unroll
        for (int i = 0; i < 16; ++i) {
            m = fmaxf(m, fabsf(wv[i].x));
            m = fmaxf(m, fabsf(wv[i].y));
            m = fmaxf(m, fabsf(wv[i].z));
            m = fmaxf(m, fabsf(wv[i].w));
        }
        m = fmaxf(m, __shfl_xor_sync(0xffffffffu, m, 1));
        m = fmaxf(m, __shfl_xor_sync(0xffffffffu, m, 2));
        const float scale = fmaxf(m / 7.0f, 1e-9f);
        const float rcp   = 1.0f / scale;

        __syncthreads();   // previous group's LDSM reads done before smem overwrite

        // ---- stage x hi/lo tiles (precomputed bf16): 8 LDG.128 + 8 STS.128 per thread ----
        #pragma unroll
        for (int j = 0; j < 4; ++j) {
            const int u = xcu + 8 * j;   // 16B unit 0..31
            uint4 vh = *(const uint4*)(xsrc_h + kb + u * 8);
            *(uint4*)((char*)&sxh[xr][0] + u * 16) = vh;
        }
        #pragma unroll
        for (int j = 0; j < 4; ++j) {
            const int u = xcu + 8 * j;
            uint4 vl = *(const uint4*)(xsrc_l + kb + u * 8);
            *(uint4*)((char*)&sxl[xr][0] + u * 16) = vl;
        }

        // ---- quantize W -> bf16 w_int into smem (1 cvt per pair) ----
        #pragma unroll
        for (int i = 0; i < 16; ++i) {
            const int col = (wc + 4 * i) * 4;
            const float4 v = wv[i];
            float q0 = fminf(fmaxf(rintf(v.x * rcp), -8.f), 7.f);
            float q1 = fminf(fmaxf(rintf(v.y * rcp), -8.f), 7.f);
            float q2 = fminf(fmaxf(rintf(v.z * rcp), -8.f), 7.f);
            float q3 = fminf(fmaxf(rintf(v.w * rcp), -8.f), 7.f);
            uint2 pk;
            pk.x = cvt_bf16x2(q0, q1);
            pk.y = cvt_bf16x2(q2, q3);
            *(uint2*)&swq[wr][col] = pk;
        }
        if (wc == 0) sscale[wr] = scale;

        // ---- prefetch next W tile (wv dead after quantize; overlaps MMA phase) ----
        if (g + 1 < NGROUPS) {
            const int kbn = kb + GSIZE;
            #pragma unroll
            for (int i = 0; i < 16; ++i)
                wv[i] = *(const float4*)(wrow + kbn + (wc + 4 * i) * 4);
        }

        __syncthreads();

        // ---- MMA phase: 16 k-steps x (hi + lo), group-local fp32 accumulators ----
        float p0 = 0.f, p1 = 0.f, p2 = 0.f, p3 = 0.f;
        #pragma unroll
        for (int ks = 0; ks < 16; ++ks) {
            const uint32_t boff = ks * 32;  // 16 bf16 = 32 bytes per k-step
            uint32_t b0, b1;
            ldsm_x2(b0, b1, a_b + boff);

            uint32_t h0, h1, h2, h3;
            ldsm_x4(h0, h1, h2, h3, a_xh + boff);
            mma16816(p0, p1, p2, p3, h0, h1, h2, h3, b0, b1);

            uint32_t l0, l1, l2, l3;
            ldsm_x4(l0, l1, l2, l3, a_xl + boff);
            mma16816(p0, p1, p2, p3, l0, l1, l2, l3, b0, b1);
        }

        // scale per output column (o), accumulate into final
        const float se = sscale[wid * 8 + 2 * tg];
        const float so = sscale[wid * 8 + 2 * tg + 1];
        facc0 += se * p0;
        facc1 += so * p1;
        facc2 += se * p2;
        facc3 += so * p3;
    }

    // ---- epilogue: D[s][o] -> out[s*ODIM + o] ----
    const int ocol = obase + wid * 8 + 2 * tg;
    const int r0 = gid;
    const int r1 = gid + 8;
    *(float2*)(out + (size_t)r0 * ODIM + ocol) = make_float2(facc0, facc1);
    *(float2*)(out + (size_t)r1 * ODIM + ocol) = make_float2(facc2, facc3);
}

extern "C" void kernel_launch(void* const* d_in, const int* in_sizes, int n_in,
                              void* d_out, int out_size)
{
    (void)in_sizes; (void)n_in; (void)out_size;
    const float* x = (const float*)d_in[0];   // [1,16,4096]
    const float* w = (const float*)d_in[1];   // [14336,4096]
    float* out = (float*)d_out;               // [1,16,14336]

    // prologue: precompute x hi/lo bf16 (16384 float4s / 256 thr = 64 blocks)
    xsplit_kernel<<<(SDIM * KDIM) / (256 * 4), 256>>>(x);

    dim3 grid(ODIM / TILE_O);  // 448
    dim3 block(NTHREADS);      // 128
    qlinear_int4_kernel<<<grid, block>>>(w, out);
}

// round 7
// speedup vs baseline: 1.8122x; 1.0885x over previous
#include <cuda_runtime.h>
#include <cuda_bf16.h>
#include <stdint.h>

#define SDIM    16
#define KDIM    4096
#define ODIM    14336
#define GSIZE   256
#define NGROUPS (KDIM / GSIZE)   // 16
#define TILE_O  32
#define NTHREADS 256
#define STRIDE  264              // bf16 elems per smem row; 528B row stride -> 4-bank shift/row, LDSM conflict-free

// Precomputed x split into bf16 hi + lo residual (written by prologue kernel)
__device__ __align__(16) __nv_bfloat16 g_xh[SDIM * KDIM];
__device__ __align__(16) __nv_bfloat16 g_xl[SDIM * KDIM];

static __device__ __forceinline__ uint32_t packbf(__nv_bfloat16 a, __nv_bfloat16 b) {
    __nv_bfloat162 t = __halves2bfloat162(a, b);
    return *reinterpret_cast<uint32_t*>(&t);
}

// pack two fp32 -> bf16x2 in ONE cvt (result = {lo=a, hi=b})
static __device__ __forceinline__ uint32_t cvt_bf16x2(float a, float b) {
    uint32_t r;
    asm("cvt.rn.bf16x2.f32 %0, %1, %2;" : "=r"(r) : "f"(b), "f"(a));
    return r;
}

static __device__ __forceinline__ void mma16816(
    float& d0, float& d1, float& d2, float& d3,
    uint32_t a0, uint32_t a1, uint32_t a2, uint32_t a3,
    uint32_t b0, uint32_t b1)
{
    asm volatile(
        "mma.sync.aligned.m16n8k16.row.col.f32.bf16.bf16.f32 "
        "{%0,%1,%2,%3}, {%4,%5,%6,%7}, {%8,%9}, {%0,%1,%2,%3};\n"
        : "+f"(d0), "+f"(d1), "+f"(d2), "+f"(d3)
        : "r"(a0), "r"(a1), "r"(a2), "r"(a3), "r"(b0), "r"(b1));
}

static __device__ __forceinline__ void ldsm_x4(
    uint32_t& r0, uint32_t& r1, uint32_t& r2, uint32_t& r3, uint32_t saddr)
{
    asm volatile("ldmatrix.sync.aligned.m8n8.x4.shared.b16 {%0,%1,%2,%3}, [%4];\n"
        : "=r"(r0), "=r"(r1), "=r"(r2), "=r"(r3) : "r"(saddr));
}

static __device__ __forceinline__ void ldsm_x2(
    uint32_t& r0, uint32_t& r1, uint32_t saddr)
{
    asm volatile("ldmatrix.sync.aligned.m8n8.x2.shared.b16 {%0,%1}, [%2];\n"
        : "=r"(r0), "=r"(r1) : "r"(saddr));
}

// Prologue: split x into bf16 hi/lo (16384 float4s over 64 blocks x 256 thr)
__global__ void xsplit_kernel(const float* __restrict__ x)
{
    const int t = blockIdx.x * 256 + threadIdx.x;   // 0..16383, one float4 each
    const float4 v = ((const float4*)x)[t];
    __nv_bfloat16 hx = __float2bfloat16_rn(v.x);
    __nv_bfloat16 hy = __float2bfloat16_rn(v.y);
    __nv_bfloat16 hz = __float2bfloat16_rn(v.z);
    __nv_bfloat16 hw = __float2bfloat16_rn(v.w);
    uint2 hv;
    hv.x = packbf(hx, hy);
    hv.y = packbf(hz, hw);
    *(uint2*)&g_xh[t * 4] = hv;
    uint2 lv;
    lv.x = cvt_bf16x2(v.x - __bfloat162float(hx), v.y - __bfloat162float(hy));
    lv.y = cvt_bf16x2(v.z - __bfloat162float(hz), v.w - __bfloat162float(hw));
    *(uint2*)&g_xl[t * 4] = lv;
}

__global__ void __launch_bounds__(NTHREADS, 3)
qlinear_int4_kernel(const float* __restrict__ w, float* __restrict__ out)
{
    __shared__ __nv_bfloat16 sxh[SDIM][STRIDE];   // x high bf16
    __shared__ __nv_bfloat16 sxl[SDIM][STRIDE];   // x low  bf16 (residual)
    __shared__ __nv_bfloat16 swq[TILE_O][STRIDE]; // quantized w_int as bf16
    __shared__ float sscale[TILE_O];
    __shared__ float sred[4][32][4];              // cross-warp split-K reduction

    const int tid  = threadIdx.x;
    const int lane = tid & 31;
    const int wid  = tid >> 5;       // warp 0..7
    const int nw   = wid & 3;        // n8 tile index
    const int kwh  = wid >> 2;       // k-half: 0 = k-steps 0..7, 1 = k-steps 8..15
    const int tg   = lane & 3;       // 0..3
    const int gid  = lane >> 2;      // 0..7
    const int obase = blockIdx.x * TILE_O;

    // W tile load mapping: 8 threads per output row, 16B each, coalesced
    const int wr = tid >> 3;         // row in tile 0..31
    const int wc = tid & 7;          // chunk 0..7
    const float* wrow = w + (size_t)(obase + wr) * KDIM;

    // x staging mapping: first 128 threads copy hi, second 128 copy lo; 8 threads/row, 4x16B each
    const int tsel = tid >> 7;       // 0 = hi, 1 = lo
    const int t7   = tid & 127;
    const int xr   = t7 >> 3;        // 0..15
    const int xcu  = t7 & 7;         // base 16B-unit
    const __nv_bfloat16* xsrc = (tsel ? g_xl : g_xh) + (size_t)xr * KDIM;
    char* xdst = (char*)(tsel ? &sxl[xr][0] : &sxh[xr][0]);

    float facc0 = 0.f, facc1 = 0.f, facc2 = 0.f, facc3 = 0.f;

    // ldmatrix base addresses (shared space); k-half offset = 8 k-steps * 32B = 256B
    const uint32_t khoff = kwh * 256;
    const uint32_t a_xh = (uint32_t)__cvta_generic_to_shared(&sxh[lane & 15][8 * (lane >> 4)]) + khoff;
    const uint32_t a_xl = (uint32_t)__cvta_generic_to_shared(&sxl[lane & 15][8 * (lane >> 4)]) + khoff;
    const uint32_t a_b  = (uint32_t)__cvta_generic_to_shared(&swq[nw * 8 + (lane & 7)][8 * ((lane >> 3) & 1)]) + khoff;

    // ---- prologue: load group 0 W into registers ----
    float4 wv[8];
    #pragma unroll
    for (int i = 0; i < 8; ++i)
        wv[i] = *(const float4*)(wrow + (wc + 8 * i) * 4);

    for (int g = 0; g < NGROUPS; ++g) {
        const int kb = g * GSIZE;

        // ---- per-row group max (thread-local over 32 vals + 3x shfl across the 8-lane row group)
        float m = 0.f;
        #pragma unroll
        for (int i = 0; i < 8; ++i) {
            m = fmaxf(m, fabsf(wv[i].x));
            m = fmaxf(m, fabsf(wv[i].y));
            m = fmaxf(m, fabsf(wv[i].z));
            m = fmaxf(m, fabsf(wv[i].w));
        }
        m = fmaxf(m, __shfl_xor_sync(0xffffffffu, m, 1));
        m = fmaxf(m, __shfl_xor_sync(0xffffffffu, m, 2));
        m = fmaxf(m, __shfl_xor_sync(0xffffffffu, m, 4));
        const float scale = fmaxf(m / 7.0f, 1e-9f);
        const float rcp   = 1.0f / scale;

        __syncthreads();   // previous group's LDSM reads done before smem overwrite

        // ---- stage x hi/lo tiles (precomputed bf16): 4 LDG.128 + 4 STS.128 per thread ----
        #pragma unroll
        for (int j = 0; j < 4; ++j) {
            const int u = xcu + 8 * j;   // 16B unit 0..31
            uint4 v = *(const uint4*)(xsrc + kb + u * 8);
            *(uint4*)(xdst + u * 16) = v;
        }

        // ---- quantize W -> bf16 w_int into smem (1 cvt per pair) ----
        #pragma unroll
        for (int i = 0; i < 8; ++i) {
            const int col = (wc + 8 * i) * 4;
            const float4 v = wv[i];
            float q0 = fminf(fmaxf(rintf(v.x * rcp), -8.f), 7.f);
            float q1 = fminf(fmaxf(rintf(v.y * rcp), -8.f), 7.f);
            float q2 = fminf(fmaxf(rintf(v.z * rcp), -8.f), 7.f);
            float q3 = fminf(fmaxf(rintf(v.w * rcp), -8.f), 7.f);
            uint2 pk;
            pk.x = cvt_bf16x2(q0, q1);
            pk.y = cvt_bf16x2(q2, q3);
            *(uint2*)&swq[wr][col] = pk;
        }
        if (wc == 0) sscale[wr] = scale;

        // ---- prefetch next W tile (wv dead after quantize; overlaps MMA phase) ----
        if (g + 1 < NGROUPS) {
            const int kbn = kb + GSIZE;
            #pragma unroll
            for (int i = 0; i < 8; ++i)
                wv[i] = *(const float4*)(wrow + kbn + (wc + 8 * i) * 4);
        }

        __syncthreads();

        // ---- MMA phase: 8 k-steps (this warp's k-half) x (hi + lo) ----
        float p0 = 0.f, p1 = 0.f, p2 = 0.f, p3 = 0.f;
        #pragma unroll
        for (int ks = 0; ks < 8; ++ks) {
            const uint32_t boff = ks * 32;  // 16 bf16 = 32 bytes per k-step
            uint32_t b0, b1;
            ldsm_x2(b0, b1, a_b + boff);

            uint32_t h0, h1, h2, h3;
            ldsm_x4(h0, h1, h2, h3, a_xh + boff);
            mma16816(p0, p1, p2, p3, h0, h1, h2, h3, b0, b1);

            uint32_t l0, l1, l2, l3;
            ldsm_x4(l0, l1, l2, l3, a_xl + boff);
            mma16816(p0, p1, p2, p3, l0, l1, l2, l3, b0, b1);
        }

        // scale per output column (o), accumulate into final
        const float se = sscale[nw * 8 + 2 * tg];
        const float so = sscale[nw * 8 + 2 * tg + 1];
        facc0 += se * p0;
        facc1 += so * p1;
        facc2 += se * p2;
        facc3 += so * p3;
    }

    // ---- epilogue: cross-warp split-K reduce, then store ----
    __syncthreads();   // last group's LDSM reads done
    if (kwh == 1) {
        sred[nw][lane][0] = facc0;
        sred[nw][lane][1] = facc1;
        sred[nw][lane][2] = facc2;
        sred[nw][lane][3] = facc3;
    }
    __syncthreads();
    if (kwh == 0) {
        facc0 += sred[nw][lane][0];
        facc1 += sred[nw][lane][1];
        facc2 += sred[nw][lane][2];
        facc3 += sred[nw][lane][3];
        const int ocol = obase + nw * 8 + 2 * tg;
        const int r0 = gid;
        const int r1 = gid + 8;
        *(float2*)(out + (size_t)r0 * ODIM + ocol) = make_float2(facc0, facc1);
        *(float2*)(out + (size_t)r1 * ODIM + ocol) = make_float2(facc2, facc3);
    }
}

extern "C" void kernel_launch(void* const* d_in, const int* in_sizes, int n_in,
                              void* d_out, int out_size)
{
    (void)in_sizes; (void)n_in; (void)out_size;
    const float* x = (const float*)d_in[0];   // [1,16,4096]
    const float* w = (const float*)d_in[1];   // [14336,4096]
    float* out = (float*)d_out;               // [1,16,14336]

    // prologue: precompute x hi/lo bf16 (16384 float4s / 256 thr = 64 blocks)
    xsplit_kernel<<<(SDIM * KDIM) / (256 * 4), 256>>>(x);

    dim3 grid(ODIM / TILE_O);  // 448
    dim3 block(NTHREADS);      // 256
    qlinear_int4_kernel<<<grid, block>>>(w, out);
}